// round 5
// baseline (speedup 1.0000x reference)
#include <cuda_runtime.h>
#include <math.h>

// ---------------------------------------------------------------------------
// DenseGAT: 2-layer GAT, N=100000 nodes, E=1600000 edges, 256 -> 64 -> 40
// CSR-by-dst; GEMM (dup-A f32x2) with fused logits; 8-wide staged gather agg.
// ---------------------------------------------------------------------------

#define MAX_NODES 100000
#define MAX_EDGES 1600000
#define SCAN_CHUNK 512
#define MAX_BLOCKS_SCAN 256

__device__ float g_z   [MAX_NODES * 64];
__device__ float g_h   [MAX_NODES * 64];
__device__ float g_el  [MAX_NODES];
__device__ float g_er  [MAX_NODES];
__device__ int   g_deg [MAX_NODES];
__device__ int   g_scan[MAX_NODES];
__device__ int   g_off [MAX_NODES + 1];
__device__ int   g_cur [MAX_NODES];
__device__ int   g_srcs[MAX_EDGES];
__device__ int   g_bsum[MAX_BLOCKS_SCAN];
__device__ int   g_boff[MAX_BLOCKS_SCAN];

// ----------------------------- f32x2 helpers ------------------------------

__device__ __forceinline__ unsigned long long pack2(float a) {
    unsigned long long r;
    asm("mov.b64 %0, {%1, %1};" : "=l"(r) : "f"(a));
    return r;
}
__device__ __forceinline__ void fma2(unsigned long long& d,
                                     unsigned long long a, unsigned long long b) {
    asm("fma.rn.f32x2 %0, %1, %2, %0;" : "+l"(d) : "l"(a), "l"(b));
}
__device__ __forceinline__ float2 unpack2(unsigned long long v) {
    float2 f;
    asm("mov.b64 {%0, %1}, %2;" : "=f"(f.x), "=f"(f.y) : "l"(v));
    return f;
}

__device__ __forceinline__ float warp_max(float v) {
#pragma unroll
    for (int o = 16; o > 0; o >>= 1)
        v = fmaxf(v, __shfl_xor_sync(0xffffffffu, v, o));
    return v;
}
__device__ __forceinline__ float warp_sum(float v) {
#pragma unroll
    for (int o = 16; o > 0; o >>= 1)
        v += __shfl_xor_sync(0xffffffffu, v, o);
    return v;
}

// ----------------------------- CSR build ----------------------------------

__global__ void hist_kernel(const int* __restrict__ dst, int E) {
    int i = blockIdx.x * blockDim.x + threadIdx.x;
    if (i < E) atomicAdd(&g_deg[dst[i]], 1);
}

// Reads g_deg then zeroes it (self-restoring state for next graph replay).
__global__ void scan_phase1(int n) {
    __shared__ int sm[SCAN_CHUNK];
    int i = blockIdx.x * SCAN_CHUNK + threadIdx.x;
    int d = (i < n) ? g_deg[i] : 0;
    if (i < n) g_deg[i] = 0;
    sm[threadIdx.x] = d;
    __syncthreads();
#pragma unroll
    for (int o = 1; o < SCAN_CHUNK; o <<= 1) {
        int t = (threadIdx.x >= o) ? sm[threadIdx.x - o] : 0;
        __syncthreads();
        sm[threadIdx.x] += t;
        __syncthreads();
    }
    if (i < n) g_scan[i] = sm[threadIdx.x];
    if (threadIdx.x == SCAN_CHUNK - 1) g_bsum[blockIdx.x] = sm[SCAN_CHUNK - 1];
}

__global__ void scan_phase2(int nb) {
    int lane = threadIdx.x;
    int base = lane * 8;
    int v[8];
    int s = 0;
#pragma unroll
    for (int j = 0; j < 8; j++) {
        int x = (base + j < nb) ? g_bsum[base + j] : 0;
        v[j] = s;
        s += x;
    }
    int t = s;
#pragma unroll
    for (int o = 1; o < 32; o <<= 1) {
        int u = __shfl_up_sync(0xffffffffu, t, o);
        if (lane >= o) t += u;
    }
    int excl = t - s;
#pragma unroll
    for (int j = 0; j < 8; j++)
        if (base + j < nb) g_boff[base + j] = excl + v[j];
}

__global__ void scan_phase3(int n) {
    int i = blockIdx.x * blockDim.x + threadIdx.x;
    if (i < n) {
        int v = g_scan[i] + g_boff[i >> 9];
        g_off[i + 1] = v;
        if (i + 1 < n) g_cur[i + 1] = v;
    }
    if (i == 0) { g_off[0] = 0; g_cur[0] = 0; }
}

__global__ void scatter_kernel(const int* __restrict__ src, const int* __restrict__ dst, int E) {
    int i = blockIdx.x * blockDim.x + threadIdx.x;
    if (i >= E) return;
    int pos = atomicAdd(&g_cur[dst[i]], 1);
    g_srcs[pos] = src[i];
}

// ----------------------------- GEMM + fused logits -------------------------
// Z[M,NOUT] = A[M,K] @ W[K,NOUT]. Block tile 128x64, 256 threads, BK=32.
// A stored in smem PRE-DUPLICATED as u64 {a,a}; B read as 2x LDS.128.
// Micro-tile: rows {ty+32i} i<4, cols 8tx..8tx+7 (4 f32x2 pairs).
// Fused: el/er attention logits via width-8 shuffle reduce in epilogue.

#define AS_STRIDE 33   // u64 units per A-tile row

template<int K, int NOUT>
__global__ void __launch_bounds__(256, 3)
gemm_fused_kernel(const float* __restrict__ A, const float* __restrict__ W,
                  const float* __restrict__ al, const float* __restrict__ ar,
                  float* __restrict__ Z, int M) {
    __shared__ unsigned long long As2[128 * AS_STRIDE];   // 33792 B
    __shared__ __align__(16) float Bs[32][64];            // 8192 B

    int tid = threadIdx.x;
    int tx  = tid & 7;      // col group: cols 8tx .. 8tx+7
    int ty  = tid >> 3;     // 0..31: rows ty + 32*i
    int m0  = blockIdx.x * 128;

    unsigned long long acc[4][4];
#pragma unroll
    for (int i = 0; i < 4; i++)
#pragma unroll
        for (int p = 0; p < 4; p++) acc[i][p] = 0ull;

    for (int k0 = 0; k0 < K; k0 += 32) {
        // A tile: 128 rows x 32 k = 1024 float4; 4 per thread; duplicate-pack.
#pragma unroll
        for (int t = 0; t < 4; t++) {
            int idx = tid + t * 256;
            int r   = idx >> 3;
            int kc  = (idx & 7) * 4;
            float4 v = make_float4(0.f, 0.f, 0.f, 0.f);
            int row = m0 + r;
            if (row < M)
                v = *(const float4*)&A[(long long)row * K + k0 + kc];
            unsigned long long* dp = &As2[r * AS_STRIDE + kc];
            dp[0] = pack2(v.x); dp[1] = pack2(v.y);
            dp[2] = pack2(v.z); dp[3] = pack2(v.w);
        }
        // B tile: 32 x 64 (pad cols >= NOUT with 0); 8 per thread.
#pragma unroll
        for (int t = 0; t < 8; t++) {
            int idx = tid + t * 256;
            int kr  = idx >> 6;
            int c   = idx & 63;
            Bs[kr][c] = (c < NOUT) ? W[(k0 + kr) * NOUT + c] : 0.f;
        }
        __syncthreads();

#pragma unroll 4
        for (int k = 0; k < 32; k++) {
            unsigned long long bp[4];
            *(ulonglong2*)&bp[0] = *(const ulonglong2*)&Bs[k][8 * tx];
            *(ulonglong2*)&bp[2] = *(const ulonglong2*)&Bs[k][8 * tx + 4];
            unsigned long long ap[4];
#pragma unroll
            for (int i = 0; i < 4; i++)
                ap[i] = As2[(ty + 32 * i) * AS_STRIDE + k];
#pragma unroll
            for (int i = 0; i < 4; i++)
#pragma unroll
                for (int p = 0; p < 4; p++)
                    fma2(acc[i][p], ap[i], bp[p]);
        }
        __syncthreads();
    }

    // attention vectors for this thread's 8 columns (epilogue-only regs)
    float alv[8], arv[8];
#pragma unroll
    for (int j = 0; j < 8; j++) {
        int col = 8 * tx + j;
        alv[j] = (col < NOUT) ? al[col] : 0.f;
        arv[j] = (col < NOUT) ? ar[col] : 0.f;
    }

#pragma unroll
    for (int i = 0; i < 4; i++) {
        int row = m0 + ty + 32 * i;
        if (row >= M) continue;
        float vals[8];
        float sl = 0.f, sr = 0.f;
#pragma unroll
        for (int p = 0; p < 4; p++) {
            float2 f = unpack2(acc[i][p]);
            vals[2 * p]     = f.x;
            vals[2 * p + 1] = f.y;
            sl += f.x * alv[2 * p] + f.y * alv[2 * p + 1];
            sr += f.x * arv[2 * p] + f.y * arv[2 * p + 1];
        }
        if (8 * tx < NOUT) {   // NOUT is a multiple of 8
            *(float4*)&Z[(long long)row * NOUT + 8 * tx]     = make_float4(vals[0], vals[1], vals[2], vals[3]);
            *(float4*)&Z[(long long)row * NOUT + 8 * tx + 4] = make_float4(vals[4], vals[5], vals[6], vals[7]);
        }
#pragma unroll
        for (int d = 4; d > 0; d >>= 1) {
            sl += __shfl_down_sync(0xffffffffu, sl, d, 8);
            sr += __shfl_down_sync(0xffffffffu, sr, d, 8);
        }
        if (tx == 0) { g_el[row] = sl; g_er[row] = sr; }
    }
}

// --------------------- fused softmax + aggregation ------------------------
// Register-staged edge chunks; 8-wide unrolled shuffle-broadcast gather with
// dual accumulators for MLP.

// Layer 1: 2 warps per node (feature halves of 64).
__global__ void fused_agg1_kernel(const float* __restrict__ Z, const float* __restrict__ b,
                                  float* __restrict__ H, int n, float neg_slope) {
    int gw   = (blockIdx.x * blockDim.x + threadIdx.x) >> 5;
    int node = gw >> 1;
    int half = gw & 1;
    int lane = threadIdx.x & 31;
    if (node >= n) return;
    int start = g_off[node], end = g_off[node + 1];
    int deg   = end - start;
    float erd = g_er[node];
    int fo = half * 32 + lane;

    float accA = 0.f, accB = 0.f, sum = 0.f;

    if (deg <= 32) {
        bool v = lane < deg;
        int   s = v ? g_srcs[start + lane] : 0;
        float e = v ? (g_el[s] + erd) : -3.4e38f;
        e = (e > 0.f) ? e : neg_slope * e;
        float m = warp_max(e);
        float w = v ? expf(e - m) : 0.f;
        sum = w;
        int cnt8 = (deg + 7) & ~7;
        for (int j = 0; j < cnt8; j += 8) {
#pragma unroll
            for (int jj = 0; jj < 8; jj += 2) {
                int   s0 = __shfl_sync(0xffffffffu, s, j + jj);
                float w0 = __shfl_sync(0xffffffffu, w, j + jj);
                int   s1 = __shfl_sync(0xffffffffu, s, j + jj + 1);
                float w1 = __shfl_sync(0xffffffffu, w, j + jj + 1);
                accA += w0 * Z[(long long)s0 * 64 + fo];
                accB += w1 * Z[(long long)s1 * 64 + fo];
            }
        }
    } else {
        float m = -3.4e38f;
        for (int i = start + lane; i < end; i += 32) {
            float e = g_el[g_srcs[i]] + erd;
            e = (e > 0.f) ? e : neg_slope * e;
            m = fmaxf(m, e);
        }
        m = warp_max(m);
        for (int c = start; c < end; c += 32) {
            int idx = c + lane;
            bool v = idx < end;
            int   s = v ? g_srcs[idx] : 0;
            float e = v ? (g_el[s] + erd) : -3.4e38f;
            e = (e > 0.f) ? e : neg_slope * e;
            float w = v ? expf(e - m) : 0.f;
            sum += w;
            int cnt  = min(32, end - c);
            int cnt8 = (cnt + 7) & ~7;
            for (int j = 0; j < cnt8; j += 8) {
#pragma unroll
                for (int jj = 0; jj < 8; jj += 2) {
                    int   s0 = __shfl_sync(0xffffffffu, s, j + jj);
                    float w0 = __shfl_sync(0xffffffffu, w, j + jj);
                    int   s1 = __shfl_sync(0xffffffffu, s, j + jj + 1);
                    float w1 = __shfl_sync(0xffffffffu, w, j + jj + 1);
                    accA += w0 * Z[(long long)s0 * 64 + fo];
                    accB += w1 * Z[(long long)s1 * 64 + fo];
                }
            }
        }
    }

    sum = warp_sum(sum);
    float sinv = (deg > 0) ? 1.f / sum : 0.f;
    float v0 = (accA + accB) * sinv + b[fo];
    H[(long long)node * 64 + fo] = (v0 > 0.f) ? v0 : 0.f;
}

// Layer 2: 1 warp per node, F = 40, fused bias + log_softmax.
__global__ void fused_agg2_kernel(const float* __restrict__ Z, const float* __restrict__ b,
                                  float* __restrict__ out, int n, float neg_slope) {
    int gw   = (blockIdx.x * blockDim.x + threadIdx.x) >> 5;
    int node = gw;
    int lane = threadIdx.x & 31;
    if (node >= n) return;
    int start = g_off[node], end = g_off[node + 1];
    int deg   = end - start;
    float erd = g_er[node];
    bool h1 = lane < 8;

    float accA = 0.f, accB = 0.f, acc1 = 0.f, sum = 0.f;

    if (deg <= 32) {
        bool v = lane < deg;
        int   s = v ? g_srcs[start + lane] : 0;
        float e = v ? (g_el[s] + erd) : -3.4e38f;
        e = (e > 0.f) ? e : neg_slope * e;
        float m = warp_max(e);
        float w = v ? expf(e - m) : 0.f;
        sum = w;
        int cnt8 = (deg + 7) & ~7;
        for (int j = 0; j < cnt8; j += 8) {
#pragma unroll
            for (int jj = 0; jj < 8; jj += 2) {
                int   s0 = __shfl_sync(0xffffffffu, s, j + jj);
                float w0 = __shfl_sync(0xffffffffu, w, j + jj);
                int   s1 = __shfl_sync(0xffffffffu, s, j + jj + 1);
                float w1 = __shfl_sync(0xffffffffu, w, j + jj + 1);
                const float* z0 = Z + (long long)s0 * 40;
                const float* z1 = Z + (long long)s1 * 40;
                accA += w0 * z0[lane];
                accB += w1 * z1[lane];
                if (h1) acc1 += w0 * z0[lane + 32] + w1 * z1[lane + 32];
            }
        }
    } else {
        float m = -3.4e38f;
        for (int i = start + lane; i < end; i += 32) {
            float e = g_el[g_srcs[i]] + erd;
            e = (e > 0.f) ? e : neg_slope * e;
            m = fmaxf(m, e);
        }
        m = warp_max(m);
        for (int c = start; c < end; c += 32) {
            int idx = c + lane;
            bool v = idx < end;
            int   s = v ? g_srcs[idx] : 0;
            float e = v ? (g_el[s] + erd) : -3.4e38f;
            e = (e > 0.f) ? e : neg_slope * e;
            float w = v ? expf(e - m) : 0.f;
            sum += w;
            int cnt  = min(32, end - c);
            int cnt8 = (cnt + 7) & ~7;
            for (int j = 0; j < cnt8; j += 8) {
#pragma unroll
                for (int jj = 0; jj < 8; jj += 2) {
                    int   s0 = __shfl_sync(0xffffffffu, s, j + jj);
                    float w0 = __shfl_sync(0xffffffffu, w, j + jj);
                    int   s1 = __shfl_sync(0xffffffffu, s, j + jj + 1);
                    float w1 = __shfl_sync(0xffffffffu, w, j + jj + 1);
                    const float* z0 = Z + (long long)s0 * 40;
                    const float* z1 = Z + (long long)s1 * 40;
                    accA += w0 * z0[lane];
                    accB += w1 * z1[lane];
                    if (h1) acc1 += w0 * z0[lane + 32] + w1 * z1[lane + 32];
                }
            }
        }
    }

    sum = warp_sum(sum);
    float sinv = (deg > 0) ? 1.f / sum : 0.f;
    float v0 = (accA + accB) * sinv + b[lane];
    float v1 = h1 ? (acc1 * sinv + b[lane + 32]) : -3.4e38f;

    float mx = warp_max(fmaxf(v0, v1));
    float se = warp_sum(expf(v0 - mx) + (h1 ? expf(v1 - mx) : 0.f));
    float lse = mx + logf(se);

    long long base = (long long)node * 40;
    out[base + lane] = v0 - lse;
    if (h1) out[base + lane + 32] = v1 - lse;
}

// ----------------------------- host launch ---------------------------------

extern "C" void kernel_launch(void* const* d_in, const int* in_sizes, int n_in,
                              void* d_out, int out_size) {
    const float* feat = (const float*)d_in[0];
    const int*   src  = (const int*)  d_in[1];
    const int*   dst  = (const int*)  d_in[2];
    const float* W1   = (const float*)d_in[3];
    const float* b1   = (const float*)d_in[4];
    const float* al1  = (const float*)d_in[5];
    const float* ar1  = (const float*)d_in[6];
    const float* W2   = (const float*)d_in[7];
    const float* b2   = (const float*)d_in[8];
    const float* al2  = (const float*)d_in[9];
    const float* ar2  = (const float*)d_in[10];
    float* out = (float*)d_out;

    const int IN = 256;
    int n = in_sizes[0] / IN;   // 100000
    int E = in_sizes[1];        // 1600000

    float* zp; cudaGetSymbolAddress((void**)&zp, g_z);
    float* hp; cudaGetSymbolAddress((void**)&hp, g_h);

    const float NEG_SLOPE = 0.2f;
    int mb128 = (n + 127) / 128;
    int nb_scan = (n + SCAN_CHUNK - 1) / SCAN_CHUNK;

    // gemm1 at stream launch index 3 (profiler's capture slot).
    hist_kernel<<<(E + 255) / 256, 256>>>(dst, E);                         // 0
    scan_phase1<<<nb_scan, SCAN_CHUNK>>>(n);                               // 1
    scan_phase2<<<1, 32>>>(nb_scan);                                       // 2
    gemm_fused_kernel<256, 64><<<mb128, 256>>>(feat, W1, al1, ar1, zp, n); // 3 <- profiled
    scan_phase3<<<(n + 255) / 256, 256>>>(n);                              // 4
    scatter_kernel<<<(E + 255) / 256, 256>>>(src, dst, E);                 // 5

    fused_agg1_kernel<<<(2 * n * 32 + 255) / 256, 256>>>(zp, b1, hp, n, NEG_SLOPE); // 6
    gemm_fused_kernel<64, 40><<<mb128, 256>>>(hp, W2, al2, ar2, zp, n);             // 7
    fused_agg2_kernel<<<(n * 32 + 255) / 256, 256>>>(zp, b2, out, n, NEG_SLOPE);    // 8
}

// round 6
// speedup vs baseline: 1.2612x; 1.2612x over previous
#include <cuda_runtime.h>
#include <math.h>

// ---------------------------------------------------------------------------
// DenseGAT: 2-layer GAT, N=100000 nodes, E=1600000 edges, 256 -> 64 -> 40
// CSR-by-dst; round-4 f32x2 GEMM (fma-floor); smem-staged MLP-8 gather agg.
// ---------------------------------------------------------------------------

#define MAX_NODES 100000
#define MAX_EDGES 1600000
#define SCAN_CHUNK 512
#define MAX_BLOCKS_SCAN 256

__device__ float g_z   [MAX_NODES * 64];
__device__ float g_h   [MAX_NODES * 64];
__device__ float g_el  [MAX_NODES];
__device__ float g_er  [MAX_NODES];
__device__ int   g_deg [MAX_NODES];
__device__ int   g_scan[MAX_NODES];
__device__ int   g_off [MAX_NODES + 1];
__device__ int   g_cur [MAX_NODES];
__device__ int   g_srcs[MAX_EDGES];
__device__ int   g_bsum[MAX_BLOCKS_SCAN];
__device__ int   g_boff[MAX_BLOCKS_SCAN];

// ----------------------------- f32x2 helpers ------------------------------

__device__ __forceinline__ unsigned long long pack2(float a) {
    unsigned long long r;
    asm("mov.b64 %0, {%1, %1};" : "=l"(r) : "f"(a));
    return r;
}
__device__ __forceinline__ void fma2(unsigned long long& d,
                                     unsigned long long a, unsigned long long b) {
    asm("fma.rn.f32x2 %0, %1, %2, %0;" : "+l"(d) : "l"(a), "l"(b));
}
__device__ __forceinline__ float2 unpack2(unsigned long long v) {
    float2 f;
    asm("mov.b64 {%0, %1}, %2;" : "=f"(f.x), "=f"(f.y) : "l"(v));
    return f;
}

__device__ __forceinline__ float warp_max(float v) {
#pragma unroll
    for (int o = 16; o > 0; o >>= 1)
        v = fmaxf(v, __shfl_xor_sync(0xffffffffu, v, o));
    return v;
}
__device__ __forceinline__ float warp_sum(float v) {
#pragma unroll
    for (int o = 16; o > 0; o >>= 1)
        v += __shfl_xor_sync(0xffffffffu, v, o);
    return v;
}

// ----------------------------- CSR build ----------------------------------

__global__ void hist_kernel(const int* __restrict__ dst, int E) {
    int i = blockIdx.x * blockDim.x + threadIdx.x;
    if (i < E) atomicAdd(&g_deg[dst[i]], 1);
}

// Reads g_deg then zeroes it (self-restoring for graph replay).
__global__ void scan_phase1(int n) {
    __shared__ int sm[SCAN_CHUNK];
    int i = blockIdx.x * SCAN_CHUNK + threadIdx.x;
    int d = (i < n) ? g_deg[i] : 0;
    if (i < n) g_deg[i] = 0;
    sm[threadIdx.x] = d;
    __syncthreads();
#pragma unroll
    for (int o = 1; o < SCAN_CHUNK; o <<= 1) {
        int t = (threadIdx.x >= o) ? sm[threadIdx.x - o] : 0;
        __syncthreads();
        sm[threadIdx.x] += t;
        __syncthreads();
    }
    if (i < n) g_scan[i] = sm[threadIdx.x];
    if (threadIdx.x == SCAN_CHUNK - 1) g_bsum[blockIdx.x] = sm[SCAN_CHUNK - 1];
}

__global__ void scan_phase2(int nb) {
    int lane = threadIdx.x;
    int base = lane * 8;
    int v[8];
    int s = 0;
#pragma unroll
    for (int j = 0; j < 8; j++) {
        int x = (base + j < nb) ? g_bsum[base + j] : 0;
        v[j] = s;
        s += x;
    }
    int t = s;
#pragma unroll
    for (int o = 1; o < 32; o <<= 1) {
        int u = __shfl_up_sync(0xffffffffu, t, o);
        if (lane >= o) t += u;
    }
    int excl = t - s;
#pragma unroll
    for (int j = 0; j < 8; j++)
        if (base + j < nb) g_boff[base + j] = excl + v[j];
}

__global__ void scan_phase3(int n) {
    int i = blockIdx.x * blockDim.x + threadIdx.x;
    if (i < n) {
        int v = g_scan[i] + g_boff[i >> 9];
        g_off[i + 1] = v;
        if (i + 1 < n) g_cur[i + 1] = v;
    }
    if (i == 0) { g_off[0] = 0; g_cur[0] = 0; }
}

__global__ void scatter_kernel(const int* __restrict__ src, const int* __restrict__ dst, int E) {
    int i = blockIdx.x * blockDim.x + threadIdx.x;
    if (i >= E) return;
    int pos = atomicAdd(&g_cur[dst[i]], 1);
    g_srcs[pos] = src[i];
}

// ----------------------------- GEMM + fused logits -------------------------
// ROUND-4 VERSION (measured 86us, at the f32x2 fma issue floor). 128 threads,
// block tile 128x64, BK=32, micro 8 rows x 4 f32x2 col-pairs.

#define A_STRIDE 36

template<int K, int NOUT>
__global__ void gemm_fused_kernel(const float* __restrict__ A, const float* __restrict__ W,
                                  const float* __restrict__ al, const float* __restrict__ ar,
                                  float* __restrict__ Z, int M) {
    __shared__ float As[128 * A_STRIDE];
    __shared__ float Bs[32][64];

    int tid = threadIdx.x;
    int tx  = tid & 7;
    int ty  = tid >> 3;
    int m0  = blockIdx.x * 128;

    float alv[8], arv[8];
#pragma unroll
    for (int p = 0; p < 4; p++) {
        int col = 2 * tx + 16 * p;
        alv[2*p]   = (col     < NOUT) ? al[col]     : 0.f;
        alv[2*p+1] = (col + 1 < NOUT) ? al[col + 1] : 0.f;
        arv[2*p]   = (col     < NOUT) ? ar[col]     : 0.f;
        arv[2*p+1] = (col + 1 < NOUT) ? ar[col + 1] : 0.f;
    }

    unsigned long long acc[8][4];
#pragma unroll
    for (int i = 0; i < 8; i++)
#pragma unroll
        for (int p = 0; p < 4; p++) acc[i][p] = 0ull;

    for (int k0 = 0; k0 < K; k0 += 32) {
#pragma unroll
        for (int t = 0; t < 8; t++) {
            int idx = tid + t * 128;
            int r   = idx >> 3;
            int kc  = (idx & 7) * 4;
            float4 v = make_float4(0.f, 0.f, 0.f, 0.f);
            int row = m0 + r;
            if (row < M)
                v = *(const float4*)&A[(long long)row * K + k0 + kc];
            *(float4*)&As[r * A_STRIDE + kc] = v;
        }
#pragma unroll
        for (int t = 0; t < 16; t++) {
            int idx = tid + t * 128;
            int kr  = idx >> 6;
            int c   = idx & 63;
            Bs[kr][c] = (c < NOUT) ? W[(k0 + kr) * NOUT + c] : 0.f;
        }
        __syncthreads();

#pragma unroll 4
        for (int k = 0; k < 32; k++) {
            unsigned long long bp[4];
#pragma unroll
            for (int p = 0; p < 4; p++)
                bp[p] = *(const unsigned long long*)&Bs[k][2 * tx + 16 * p];
#pragma unroll
            for (int i = 0; i < 8; i++) {
                unsigned long long ap = pack2(As[(ty + 16 * i) * A_STRIDE + k]);
#pragma unroll
                for (int p = 0; p < 4; p++)
                    fma2(acc[i][p], ap, bp[p]);
            }
        }
        __syncthreads();
    }

#pragma unroll
    for (int i = 0; i < 8; i++) {
        int row = m0 + ty + 16 * i;
        if (row >= M) continue;
        float sl = 0.f, sr = 0.f;
#pragma unroll
        for (int p = 0; p < 4; p++) {
            float2 f = unpack2(acc[i][p]);
            int col = 2 * tx + 16 * p;
            if (col < NOUT)
                *(float2*)&Z[(long long)row * NOUT + col] = f;
            sl += f.x * alv[2*p] + f.y * alv[2*p+1];
            sr += f.x * arv[2*p] + f.y * arv[2*p+1];
        }
#pragma unroll
        for (int d = 4; d > 0; d >>= 1) {
            sl += __shfl_down_sync(0xffffffffu, sl, d, 8);
            sr += __shfl_down_sync(0xffffffffu, sr, d, 8);
        }
        if (tx == 0) { g_el[row] = sl; g_er[row] = sr; }
    }
}

// --------------------- fused softmax + aggregation ------------------------
// Warp per (node[,feature-half]). Each 32-edge chunk: lane computes its own
// (w, src), stages to SMEM (one STS.64), then an 8-batched gather loop:
// 8x LDS.64 -> 8 independent LDGs -> 8 FMAs (MLP=8, L2-bandwidth bound).

// Layer 1: 2 warps per node (feature halves of 64), 8 warps/block.
__global__ void fused_agg1_kernel(const float* __restrict__ Z, const float* __restrict__ b,
                                  float* __restrict__ H, int n, float neg_slope) {
    __shared__ float2 stage[8][32];
    int wid  = threadIdx.x >> 5;
    int lane = threadIdx.x & 31;
    int gw   = blockIdx.x * 8 + wid;
    int node = gw >> 1;
    int half = gw & 1;
    if (node >= n) return;
    int start = g_off[node], end = g_off[node + 1];
    int deg   = end - start;
    float erd = g_er[node];
    int fo = half * 32 + lane;
    float2* st = stage[wid];

    // segment max
    float m = -3.4e38f;
    for (int i = start + lane; i < end; i += 32) {
        float e = g_el[g_srcs[i]] + erd;
        e = (e > 0.f) ? e : neg_slope * e;
        m = fmaxf(m, e);
    }
    m = warp_max(m);

    float acc = 0.f, sum = 0.f;
    for (int c = start; c < end; c += 32) {
        int idx = c + lane;
        bool v = idx < end;
        int   s = v ? g_srcs[idx] : 0;
        float e = v ? (g_el[s] + erd) : -3.4e38f;
        e = (e > 0.f) ? e : neg_slope * e;
        float w = v ? expf(e - m) : 0.f;
        sum += w;
        st[lane] = make_float2(w, __int_as_float(s));
        __syncwarp();

        int cnt = min(32, end - c);
        int j = 0;
        for (; j + 8 <= cnt; j += 8) {
            float wj[8]; long long sj[8];
#pragma unroll
            for (int u = 0; u < 8; u++) {
                float2 p = st[j + u];
                wj[u] = p.x;
                sj[u] = (long long)__float_as_int(p.y);
            }
            float zv[8];
#pragma unroll
            for (int u = 0; u < 8; u++)
                zv[u] = Z[sj[u] * 64 + fo];
#pragma unroll
            for (int u = 0; u < 8; u++)
                acc += wj[u] * zv[u];
        }
        for (; j < cnt; j++) {
            float2 p = st[j];
            acc += p.x * Z[(long long)__float_as_int(p.y) * 64 + fo];
        }
        __syncwarp();
    }

    sum = warp_sum(sum);
    float sinv = (deg > 0) ? 1.f / sum : 0.f;
    float v0 = acc * sinv + b[fo];
    H[(long long)node * 64 + fo] = (v0 > 0.f) ? v0 : 0.f;
}

// Layer 2: 1 warp per node, F = 40, fused bias + log_softmax.
__global__ void fused_agg2_kernel(const float* __restrict__ Z, const float* __restrict__ b,
                                  float* __restrict__ out, int n, float neg_slope) {
    __shared__ float2 stage[8][32];
    int wid  = threadIdx.x >> 5;
    int lane = threadIdx.x & 31;
    int node = blockIdx.x * 8 + wid;
    if (node >= n) return;
    int start = g_off[node], end = g_off[node + 1];
    int deg   = end - start;
    float erd = g_er[node];
    bool h1 = lane < 8;
    float2* st = stage[wid];

    float m = -3.4e38f;
    for (int i = start + lane; i < end; i += 32) {
        float e = g_el[g_srcs[i]] + erd;
        e = (e > 0.f) ? e : neg_slope * e;
        m = fmaxf(m, e);
    }
    m = warp_max(m);

    float acc0 = 0.f, acc1 = 0.f, sum = 0.f;
    for (int c = start; c < end; c += 32) {
        int idx = c + lane;
        bool v = idx < end;
        int   s = v ? g_srcs[idx] : 0;
        float e = v ? (g_el[s] + erd) : -3.4e38f;
        e = (e > 0.f) ? e : neg_slope * e;
        float w = v ? expf(e - m) : 0.f;
        sum += w;
        st[lane] = make_float2(w, __int_as_float(s));
        __syncwarp();

        int cnt = min(32, end - c);
        int j = 0;
        for (; j + 4 <= cnt; j += 4) {
            float wj[4]; long long sj[4];
#pragma unroll
            for (int u = 0; u < 4; u++) {
                float2 p = st[j + u];
                wj[u] = p.x;
                sj[u] = (long long)__float_as_int(p.y);
            }
            float zv[4], zh[4];
#pragma unroll
            for (int u = 0; u < 4; u++) {
                zv[u] = Z[sj[u] * 40 + lane];
                zh[u] = h1 ? Z[sj[u] * 40 + lane + 32] : 0.f;
            }
#pragma unroll
            for (int u = 0; u < 4; u++) {
                acc0 += wj[u] * zv[u];
                acc1 += wj[u] * zh[u];
            }
        }
        for (; j < cnt; j++) {
            float2 p = st[j];
            long long sjj = (long long)__float_as_int(p.y);
            acc0 += p.x * Z[sjj * 40 + lane];
            if (h1) acc1 += p.x * Z[sjj * 40 + lane + 32];
        }
        __syncwarp();
    }

    sum = warp_sum(sum);
    float sinv = (deg > 0) ? 1.f / sum : 0.f;
    float v0 = acc0 * sinv + b[lane];
    float v1 = h1 ? (acc1 * sinv + b[lane + 32]) : -3.4e38f;

    float mx = warp_max(fmaxf(v0, v1));
    float se = warp_sum(expf(v0 - mx) + (h1 ? expf(v1 - mx) : 0.f));
    float lse = mx + logf(se);

    long long base = (long long)node * 40;
    out[base + lane] = v0 - lse;
    if (h1) out[base + lane + 32] = v1 - lse;
}

// ----------------------------- host launch ---------------------------------

extern "C" void kernel_launch(void* const* d_in, const int* in_sizes, int n_in,
                              void* d_out, int out_size) {
    const float* feat = (const float*)d_in[0];
    const int*   src  = (const int*)  d_in[1];
    const int*   dst  = (const int*)  d_in[2];
    const float* W1   = (const float*)d_in[3];
    const float* b1   = (const float*)d_in[4];
    const float* al1  = (const float*)d_in[5];
    const float* ar1  = (const float*)d_in[6];
    const float* W2   = (const float*)d_in[7];
    const float* b2   = (const float*)d_in[8];
    const float* al2  = (const float*)d_in[9];
    const float* ar2  = (const float*)d_in[10];
    float* out = (float*)d_out;

    const int IN = 256;
    int n = in_sizes[0] / IN;   // 100000
    int E = in_sizes[1];        // 1600000

    float* zp; cudaGetSymbolAddress((void**)&zp, g_z);
    float* hp; cudaGetSymbolAddress((void**)&hp, g_h);

    const float NEG_SLOPE = 0.2f;
    int mb128 = (n + 127) / 128;
    int nb_scan = (n + SCAN_CHUNK - 1) / SCAN_CHUNK;

    // gemm1 at stream launch index 3 (profiler's capture slot).
    hist_kernel<<<(E + 255) / 256, 256>>>(dst, E);                         // 0
    scan_phase1<<<nb_scan, SCAN_CHUNK>>>(n);                               // 1
    scan_phase2<<<1, 32>>>(nb_scan);                                       // 2
    gemm_fused_kernel<256, 64><<<mb128, 128>>>(feat, W1, al1, ar1, zp, n); // 3 <- profiled
    scan_phase3<<<(n + 255) / 256, 256>>>(n);                              // 4
    scatter_kernel<<<(E + 255) / 256, 256>>>(src, dst, E);                 // 5

    fused_agg1_kernel<<<(2 * n + 7) / 8, 256>>>(zp, b1, hp, n, NEG_SLOPE);  // 6
    gemm_fused_kernel<64, 40><<<mb128, 128>>>(hp, W2, al2, ar2, zp, n);     // 7
    fused_agg2_kernel<<<(n + 7) / 8, 256>>>(zp, b2, out, n, NEG_SLOPE);     // 8
}